// round 7
// baseline (speedup 1.0000x reference)
#include <cuda_runtime.h>
#include <math.h>

#define BB 16
#define TT 60
#define NCLS 80
#define NBLK 768   // 48*12 + 48*3 + 48*1

__constant__ float c_anch[9][2] = {
    {12.f,16.f},{19.f,36.f},{40.f,28.f},{36.f,75.f},{76.f,55.f},
    {72.f,146.f},{142.f,110.f},{192.f,243.f},{459.f,401.f}};

__device__ double g_acc[5];   // xy, wh, obj, cls, l2 (zero-init; last block resets)
__device__ int    g_cnt;      // zero-init; last block resets

struct Sh {
    float4 sbx[TT];        // valid truth boxes (l,t,r,b)
    float  sar[TT];        // areas
    int    skey[TT];       // matched: (a<<20)|(jj<<10)|ii
    int    st[TT];         // matched: label index t
    float  svec[TT][6];    // matched: scale,fx,fy,lw,lh,cls
    int    fent[TT];       // entries filtered to this block's tile
    float  satn[9];        // atan(anchor_w/anchor_h)
    int    snv, snm, snf;
    float  red[8][5];
};

__device__ __forceinline__ float sigm(float x) { return __fdividef(1.0f, 1.0f + __expf(-x)); }
__device__ __forceinline__ float clog(float x) { return fmaxf(__logf(x), -100.0f); }
__device__ __forceinline__ float tsig(float x) {
    float t;
    asm("tanh.approx.f32 %0, %1;" : "=f"(t) : "f"(0.5f*x));
    return fmaf(0.5f, t, 0.5f);
}

template<int FS, int OID>
__device__ __forceinline__ void level_body(
    Sh* sh, int rel,
    const float* __restrict__ x, const float* __restrict__ labels,
    float& axy, float& awh, float& aobj, float& acls, float& al2)
{
    constexpr int   FS2     = FS*FS;
    constexpr int   BPP     = (FS2 + 511)/512;
    constexpr float S       = (OID==0) ? 8.f : (OID==1) ? 16.f : 32.f;
    constexpr float INV_S   = 1.f/S;
    constexpr float INV_2S  = 1.f/(2.f*S);
    constexpr float INV_FS2 = 1.f/(float)FS2;

    int tid = threadIdx.x, lane = tid & 31, wid = tid >> 5;
    int plane = rel / BPP;
    int tile  = rel - plane*BPP;
    int b = plane / 3, a = plane - 3*b;

    if (tid == 0) { sh->snv = 0; sh->snm = 0; sh->snf = 0; }
    if (tid < 9)  sh->satn[tid] = atanf(c_anch[tid][0] / c_anch[tid][1]);
    __syncthreads();

    // ---------- phase 1: per-block label prep for this (OID, b) ----------
    if (tid < TT) {
        const float* L = labels + (b*TT + tid)*5;
        float l0=L[0], l1=L[1], l2=L[2], l3=L[3], l4=L[4];
        if ((l0+l1+l2+l3+l4) > 0.0f) {
            float tx = (l2 + l0)*INV_2S;
            float ty = (l3 + l1)*INV_2S;
            float tw = (l2 - l0)*INV_S;
            float th = (l3 - l1)*INV_S;
            int slot = atomicAdd(&sh->snv, 1);
            sh->sbx[slot] = make_float4(tx - 0.5f*tw, ty - 0.5f*th,
                                        tx + 0.5f*tw, ty + 0.5f*th);
            sh->sar[slot] = tw*th;
            float area_t = tw*th;
            float best = -3.0e38f; int bi = 0;
            float at_t = atanf(tw/th);
            #pragma unroll
            for (int k = 0; k < 9; k++) {
                float aw = c_anch[k][0]*INV_S, ah = c_anch[k][1]*INV_S;
                float iw = fminf(tw, aw), ih = fminf(th, ah);
                float ai = (iw > 0.f && ih > 0.f) ? iw*ih : 0.f;
                float iou = __fdividef(ai, area_t + aw*ah - ai);
                float mw = fmaxf(tw,aw), mh = fmaxf(th,ah);
                float c2 = mw*mw + mh*mh + 1e-16f;
                float rho2 = ((tw-aw)*(tw-aw) + (th-ah)*(th-ah)) * 0.25f;
                float d = at_t - sh->satn[k];
                float v = (4.0f/(float)(M_PI*M_PI)) * d * d;
                float ciou = iou - (__fdividef(rho2, c2) + v*__fdividef(v, 1.f - iou + v));
                if (ciou > best) { best = ciou; bi = k; }
            }
            int best_n = bi - (bi/3)*3;
            if (bi/3 == OID) {
                int ii = min(max((int)tx, 0), FS-1);
                int jj = min(max((int)ty, 0), FS-1);
                int ms = atomicAdd(&sh->snm, 1);
                sh->skey[ms] = (best_n << 20) | (jj << 10) | ii;
                sh->st[ms]   = tid;
                float aw = c_anch[3*OID+best_n][0]*INV_S;
                float ah = c_anch[3*OID+best_n][1]*INV_S;
                sh->svec[ms][0] = sqrtf(2.f - tw*th*INV_FS2);
                sh->svec[ms][1] = tx - truncf(tx);
                sh->svec[ms][2] = ty - truncf(ty);
                sh->svec[ms][3] = __logf(tw/aw + 1e-16f);
                sh->svec[ms][4] = __logf(th/ah + 1e-16f);
                sh->svec[ms][5] = l4;
            }
        }
    }
    __syncthreads();
    int nv = sh->snv, nm = sh->snm;
    int p0 = tile*512;

    // filter matched entries to this block's (anchor, 512-cell tile)
    if (tid < nm) {
        int key = sh->skey[tid];
        if ((key >> 20) == a) {
            int cell = ((key >> 10) & 1023)*FS + (key & 1023);
            if (cell >= p0 && cell < p0 + 512) {
                int f = atomicAdd(&sh->snf, 1);
                sh->fent[f] = tid;
            }
        }
    }
    __syncthreads();
    int nf = sh->snf;
    int hm = (nm > 0);
    unsigned full = 0xffffffffu;

    // ---------- phase 2: two cells per thread ----------
    float o0[2], o1[2], o2v[2], o3v[2], o4v[2];
    bool  inb[2];
    int   pcx[2], ci[2], cj[2], mslot[2];
    const float* xplane = x + (size_t)(b*255 + a*85)*FS2;

    #pragma unroll
    for (int q = 0; q < 2; q++) {
        int p = p0 + q*256 + tid;
        inb[q] = (p < FS2);
        int pc_ = inb[q] ? p : (FS2 - 1);
        pcx[q] = pc_;
        ci[q] = pc_ / FS; cj[q] = pc_ - ci[q]*FS;
        const float* xb = xplane + pc_;
        o0[q] = xb[0];
        o1[q] = xb[FS2];
        o2v[q] = xb[2*FS2];
        o3v[q] = xb[3*FS2];
        o4v[q] = xb[4*FS2];
        // match resolve (tiny filtered list; last-wins = max t)
        int myKey = (a << 20) | (ci[q] << 10) | cj[q];
        int ms = -1, mT = -1;
        for (int f = 0; f < nf; f++) {
            int e = sh->fent[f];
            if (sh->skey[e] == myKey && sh->st[e] > mT) { mT = sh->st[e]; ms = e; }
        }
        mslot[q] = (inb[q] ? ms : -1);
    }

    float anw = c_anch[3*OID+a][0]*INV_S;
    float anh = c_anch[3*OID+a][1]*INV_S;

    // per-cell fast transforms
    float sxf[2], syf[2], hw[2], hh[2], Ev[2];
    #pragma unroll
    for (int q = 0; q < 2; q++) {
        sxf[q] = tsig(o0[q]);
        syf[q] = tsig(o1[q]);
        Ev[q]  = __expf(o4v[q]);
        hw[q]  = 0.5f*__expf(o2v[q])*anw;
        hh[q]  = 0.5f*__expf(o3v[q])*anh;
    }

    unsigned m0 = 0u, m1 = 0u;
    if (hm) {
        // warp bbox: static center bounds from contiguous index runs + reduced max half-sizes
        int imn = 1<<30, imx = -1, jmn = 1<<30, jmx = -1;
        #pragma unroll
        for (int q = 0; q < 2; q++) {
            int first = p0 + q*256 + wid*32;
            if (first < FS2) {
                int last = min(first + 31, FS2 - 1);
                int i_f = first / FS, i_l = last / FS;
                imn = min(imn, i_f); imx = max(imx, i_l);
                if (i_f == i_l) { jmn = min(jmn, first - i_f*FS); jmx = max(jmx, last - i_l*FS); }
                else            { jmn = 0; jmx = FS - 1; }
            }
        }
        float mhw = fmaxf(inb[0] ? hw[0] : 0.f, inb[1] ? hw[1] : 0.f);
        float mhh = fmaxf(inb[0] ? hh[0] : 0.f, inb[1] ? hh[1] : 0.f);
        #pragma unroll
        for (int off = 16; off; off >>= 1) {
            mhw = fmaxf(mhw, __shfl_xor_sync(full, mhw, off));
            mhh = fmaxf(mhh, __shfl_xor_sync(full, mhh, off));
        }
        float xlo = (float)jmn - mhw, xhi = (float)(jmx+1) + mhw;
        float ylo = (float)imn - mhh, yhi = (float)(imx+1) + mhh;
        bool c0 = false, c1 = false;
        if (lane < nv) {
            float4 tb = sh->sbx[lane];
            c0 = (tb.x < xhi) && (tb.z > xlo) && (tb.y < yhi) && (tb.w > ylo);
        }
        if (lane + 32 < nv) {
            float4 tb = sh->sbx[lane + 32];
            c1 = (tb.x < xhi) && (tb.z > xlo) && (tb.y < yhi) && (tb.w > ylo);
        }
        m0 = __ballot_sync(full, c0);
        m1 = __ballot_sync(full, c1);
    }

    #pragma unroll
    for (int q = 0; q < 2; q++) {
        bool matched = (mslot[q] >= 0);
        if (inb[q] && !matched) {
            int om = 1;
            if (hm) {
                float px = sxf[q] + (float)cj[q];
                float py = syf[q] + (float)ci[q];
                float pl = px - hw[q], pr = px + hw[q];
                float pt = py - hh[q], pb = py + hh[q];
                float areap = 4.f*hw[q]*hh[q];
                unsigned mm = m0;
                while (mm) {
                    int t = __ffs(mm) - 1; mm &= mm - 1;
                    float4 tb = sh->sbx[t];
                    float dxw = fminf(pr, tb.z) - fmaxf(pl, tb.x);
                    float dyh = fminf(pb, tb.w) - fmaxf(pt, tb.y);
                    if (dxw > 0.f && dyh > 0.f && 3.0f*dxw*dyh > areap + sh->sar[t]) { om = 0; break; }
                }
                mm = om ? m1 : 0u;
                while (mm) {
                    int t = __ffs(mm) - 1 + 32; mm &= mm - 1;
                    float4 tb = sh->sbx[t];
                    float dxw = fminf(pr, tb.z) - fmaxf(pl, tb.x);
                    float dyh = fminf(pb, tb.w) - fmaxf(pt, tb.y);
                    if (dxw > 0.f && dyh > 0.f && 3.0f*dxw*dyh > areap + sh->sar[t]) { om = 0; break; }
                }
            }
            if (om) {
                float onePlusE = 1.f + Ev[q];
                float sobj = 1.f - __fdividef(1.f, onePlusE);   // = sigm(o4)
                aobj += fminf(__logf(onePlusE), 100.f);          // = -clog(1-sobj)
                al2  += sobj*sobj;
            }
        } else if (matched) {
            // precise path (rare)
            float sx = sigm(o0[q]), sy = sigm(o1[q]), sobj = sigm(o4v[q]);
            float sc = sh->svec[mslot[q]][0], fx = sh->svec[mslot[q]][1], fy = sh->svec[mslot[q]][2];
            float lw = sh->svec[mslot[q]][3], lh = sh->svec[mslot[q]][4];
            aobj += -clog(sobj);
            float dob = sobj - 1.f;
            al2 += dob*dob;
            float w = sc*sc;
            axy += -w*(fx*clog(sx) + (1.f-fx)*clog(1.f-sx));
            axy += -w*(fy*clog(sy) + (1.f-fy)*clog(1.f-sy));
            float dx = sx - fx, dy = sy - fy;
            al2 += dx*dx + dy*dy;
            float dw = sc*(o2v[q] - lw), dh = sc*(o3v[q] - lh);
            awh += 0.5f*(dw*dw + dh*dh);
            al2 += dw*dw + dh*dh;
        }
        // warp-cooperative class loss for matched cells
        unsigned mball = __ballot_sync(full, matched);
        while (mball) {
            int src = __ffs(mball) - 1; mball &= mball - 1;
            int spc = __shfl_sync(full, pcx[q],   src);
            int sl  = __shfl_sync(full, mslot[q], src);
            int cls = (int)sh->svec[sl][5];
            const float* xc = xplane + spc + 5*FS2;
            float oa  = xc[(size_t)lane*FS2];
            float obv = xc[(size_t)(lane+32)*FS2];
            float ocv = (lane < 16) ? xc[(size_t)(lane+64)*FS2] : 0.f;
            {
                float pcv = sigm(oa);
                float tc = (lane == cls) ? 1.f : 0.f;
                acls += -(tc*clog(pcv) + (1.f-tc)*clog(1.f-pcv));
                float dc = pcv - tc; al2 += dc*dc;
            }
            {
                float pcv = sigm(obv);
                float tc = (lane + 32 == cls) ? 1.f : 0.f;
                acls += -(tc*clog(pcv) + (1.f-tc)*clog(1.f-pcv));
                float dc = pcv - tc; al2 += dc*dc;
            }
            if (lane < 16) {
                float pcv = sigm(ocv);
                float tc = (lane + 64 == cls) ? 1.f : 0.f;
                acls += -(tc*clog(pcv) + (1.f-tc)*clog(1.f-pcv));
                float dc = pcv - tc; al2 += dc*dc;
            }
        }
    }
}

__global__ __launch_bounds__(256) void yolo_k(
    const float* __restrict__ x0, const float* __restrict__ x1,
    const float* __restrict__ x2, const float* __restrict__ labels,
    float* __restrict__ out)
{
    extern __shared__ char smem[];
    Sh* sh = (Sh*)smem;

    float axy=0.f, awh=0.f, aobj=0.f, acls=0.f, al2=0.f;
    int bid = blockIdx.x;
    if (bid < 576)      level_body<76,0>(sh, bid,       x0, labels, axy, awh, aobj, acls, al2);
    else if (bid < 720) level_body<38,1>(sh, bid - 576, x1, labels, axy, awh, aobj, acls, al2);
    else                level_body<19,2>(sh, bid - 720, x2, labels, axy, awh, aobj, acls, al2);

    int tid = threadIdx.x, lane = tid & 31, wid = tid >> 5;
    unsigned full = 0xffffffffu;
    #pragma unroll
    for (int off = 16; off; off >>= 1) {
        axy  += __shfl_down_sync(full, axy,  off);
        awh  += __shfl_down_sync(full, awh,  off);
        aobj += __shfl_down_sync(full, aobj, off);
        acls += __shfl_down_sync(full, acls, off);
        al2  += __shfl_down_sync(full, al2,  off);
    }
    if (lane == 0) {
        sh->red[wid][0]=axy; sh->red[wid][1]=awh; sh->red[wid][2]=aobj;
        sh->red[wid][3]=acls; sh->red[wid][4]=al2;
    }
    __syncthreads();
    if (tid == 0) {
        float s0=0.f,s1=0.f,s2=0.f,s3=0.f,s4=0.f;
        #pragma unroll
        for (int k = 0; k < 8; k++) {
            s0 += sh->red[k][0]; s1 += sh->red[k][1]; s2 += sh->red[k][2];
            s3 += sh->red[k][3]; s4 += sh->red[k][4];
        }
        atomicAdd(&g_acc[0], (double)s0);
        atomicAdd(&g_acc[1], (double)s1);
        atomicAdd(&g_acc[2], (double)s2);
        atomicAdd(&g_acc[3], (double)s3);
        atomicAdd(&g_acc[4], (double)s4);
        __threadfence();
        int old = atomicAdd(&g_cnt, 1);
        if (old == NBLK - 1) {
            float xy  = (float)g_acc[0];
            float wh  = (float)g_acc[1];
            float obj = (float)g_acc[2];
            float cls = (float)g_acc[3];
            float l2  = (float)g_acc[4];
            out[0] = xy + wh + obj + cls;
            out[1] = xy;
            out[2] = wh;
            out[3] = obj;
            out[4] = cls;
            out[5] = l2;
            g_acc[0]=0.0; g_acc[1]=0.0; g_acc[2]=0.0; g_acc[3]=0.0; g_acc[4]=0.0;
            g_cnt = 0;
        }
    }
}

extern "C" void kernel_launch(void* const* d_in, const int* in_sizes, int n_in,
                              void* d_out, int out_size) {
    const float* x0     = (const float*)d_in[0];
    const float* x1     = (const float*)d_in[1];
    const float* x2     = (const float*)d_in[2];
    const float* labels = (const float*)d_in[3];
    float* out = (float*)d_out;
    yolo_k<<<NBLK, 256, sizeof(Sh)>>>(x0, x1, x2, labels, out);
}